// round 10
// baseline (speedup 1.0000x reference)
#include <cuda_runtime.h>
#include <cstdint>
#include <cstddef>

// Problem dims
#define BB    64
#define TT    512
#define IDIM  512
#define HH    512
#define RING  8

// Tiling
#define TM    16
#define TN    32
#define NBAND (BB/TM)       // 4
#define NQ    (HH/TN)       // 16  (CTA-level releases; consumer waits for 16)
#define NCTA  128
#define NTHR  256

#define AS_STRIDE 1028
#define RMS 34              // Red m-stride -> conflict-free partial STS
#define RWS (16*RMS)

// SMEM layout (floats)
#define AS_OFF  0
#define WS_OFF  (TM*AS_STRIDE)
#define RED_OFF (WS_OFF + 512*64)
#define SMEM_FLOATS (RED_OFF + 8*RWS)

__device__ float g_h1[RING][BB][HH];
__device__ int   g_done1[TT*NBAND];
__device__ int   g_done2[TT*NBAND];

__global__ void rnn_init_counters() {
    int i = blockIdx.x * blockDim.x + threadIdx.x;
    if (i < TT*NBAND) { g_done1[i] = 0; g_done2[i] = 0; }
}

__device__ __forceinline__ int ld_acq(const int* p) {
    int v;
    asm volatile("ld.acquire.gpu.global.u32 %0, [%1];" : "=r"(v) : "l"(p));
    return v;
}
__device__ __forceinline__ void red_release(int* p) {
    asm volatile("red.release.gpu.global.add.u32 [%0], %1;" :: "l"(p), "r"(1) : "memory");
}
__device__ __forceinline__ void spin_ge(const int* p, int target) {
    while (ld_acq(p) < target) { }
}
__device__ __forceinline__ void fma2(unsigned long long& acc,
                                     unsigned long long a, unsigned long long b) {
    asm("fma.rn.f32x2 %0, %1, %2, %0;" : "+l"(acc) : "l"(a), "l"(b));
}
__device__ __forceinline__ float4 ldcg4(const float* p) {
    return __ldcg((const float4*)p);
}

// tanh(x) = 1 - 2/(exp(2x)+1); ex2.approx + rcp.approx + 1 Newton (abs err ~1e-7)
__device__ __forceinline__ float fast_tanh(float v) {
    float e;
    asm("ex2.approx.f32 %0, %1;" : "=f"(e) : "f"(v * 2.8853900817779268f));
    float d = e + 1.0f;
    float r;
    asm("rcp.approx.f32 %0, %1;" : "=f"(r) : "f"(d));
    r = r * (2.0f - d * r);
    return 1.0f - 2.0f * r;
}

// Store one float4 (k = 4*kk..4*kk+3 of row mm) into swizzled row-major As.
__device__ __forceinline__ void stage_f4(float* As, int mm, int kk, float4 v) {
    int idx = (kk*4) ^ ((mm >> 2) * 8);
    *(float4*)&As[mm*AS_STRIDE + idx] = v;
}

__global__ void __launch_bounds__(NTHR, 1) rnn_persistent(
    const float* __restrict__ x,    // [B,T,I]
    const float* __restrict__ h0,   // [L,B,H]
    const float* __restrict__ Wih,  // [L,H,I]
    const float* __restrict__ bih,  // [L,H]
    const float* __restrict__ Whh,  // [L,H,H]
    const float* __restrict__ bhh,  // [L,H]
    float* __restrict__ out)        // [B,T,H] then [L,B,H]
{
    extern __shared__ float smem[];
    float* As  = smem + AS_OFF;   // [16][1028] row-major, k-index XOR-swizzled
    float* Ws  = smem + WS_OFF;   // [512 kp][64]
    float* Red = smem + RED_OFF;  // [8 w][16 m x RMS]

    const int bx    = blockIdx.x;
    const int layer = bx >> 6;
    const int j     = bx & 63;
    const int r     = j >> 4;
    const int q     = j & 15;
    const int tid   = threadIdx.x;
    const int w     = tid >> 5;          // warp id = k-slice: kp in [64w, 64w+64)
    const int lane  = tid & 31;
    const int rg    = lane & 3;
    const int cg    = lane >> 2;

    const float* Wi = Wih + (size_t)layer * HH * IDIM;
    const float* Wh = Whh + (size_t)layer * HH * HH;

    // one-time weight load: k-paired transposed; kp 0..255 = Wih, 256..511 = Whh
    for (int idx = tid; idx < TN*256; idx += NTHR) {
        int c   = idx >> 8;
        int kpl = idx & 255;
        float2 vi = __ldg((const float2*)(Wi + (size_t)(q*TN + c)*IDIM) + kpl);
        float2 vh = __ldg((const float2*)(Wh + (size_t)(q*TN + c)*HH)   + kpl);
        *(float2*)&Ws[(size_t)kpl*64 + c*2]       = vi;
        *(float2*)&Ws[(size_t)(256+kpl)*64 + c*2] = vh;
    }

    // staging constants: thread stages f4-column kk_st for rows m0_st, m0_st+2, ...
    const int kk_st = tid & 127;
    const int m0_st = tid >> 7;

    // output mapping: 2 outputs per thread
    const int o0     = 2*tid;
    const int m_out  = o0 >> 5;
    const int c_out  = o0 & 31;
    const int brow_o = r*TM + m_out;
    const int hcol_o = q*TN + c_out;
    float2 bias;
    bias.x = bih[layer*HH + hcol_o]   + bhh[layer*HH + hcol_o];
    bias.y = bih[layer*HH + hcol_o+1] + bhh[layer*HH + hcol_o+1];

    __syncthreads();

    const float* Ab = As + (4*rg)*AS_STRIDE;
    const int    xr = 8*rg;

    // ---- prologue: stage the t=0 low K-half (off-path operand) ----
    if (layer == 0) {
        #pragma unroll
        for (int c = 0; c < 8; ++c) {
            int mm = m0_st + 2*c;
            float4 v = __ldg((const float4*)(x + ((size_t)(r*TM+mm)*TT + 0)*IDIM) + kk_st);
            stage_f4(As, mm, kk_st, v);
        }
    } else {
        if (lane == 0) spin_ge(&g_done1[0*NBAND + r], NQ);
        __syncwarp();
        #pragma unroll
        for (int c = 0; c < 8; ++c) {
            int mm = m0_st + 2*c;
            stage_f4(As, mm, kk_st, ldcg4(&g_h1[0][r*TM+mm][0] + kk_st*4));
        }
    }

    for (int t = 0; t < TT; ++t) {
        // ---- on-path wait (per-warp) + stage recurrent K-half only ----
        if (layer == 0) {
            if (lane == 0) {
                if (t > 0)     spin_ge(&g_done1[(t-1)*NBAND + r], NQ);
                if (t >= RING) spin_ge(&g_done2[(t-RING)*NBAND + r], NQ);
            }
            __syncwarp();
            #pragma unroll
            for (int c = 0; c < 8; ++c) {
                int mm = m0_st + 2*c;
                int b  = r*TM + mm;
                const float* hp = (t == 0) ? (h0 + (size_t)b*HH)
                                           : &g_h1[(t-1)&(RING-1)][b][0];
                stage_f4(As, mm, 128 + kk_st, ldcg4(hp + kk_st*4));
            }
        } else {
            if (lane == 0 && t > 0) spin_ge(&g_done2[(t-1)*NBAND + r], NQ);
            __syncwarp();
            #pragma unroll
            for (int c = 0; c < 8; ++c) {
                int mm = m0_st + 2*c;
                int b  = r*TM + mm;
                const float* hp = (t == 0) ? (h0 + (size_t)BB*HH + (size_t)b*HH)
                                           : (out + ((size_t)b*TT + (t-1))*HH);
                stage_f4(As, mm, 128 + kk_st, ldcg4(hp + kk_st*4));
            }
        }
        __syncthreads();   // bar2: staging -> GEMM

        // ---- GEMM: warp k-slice, thread 4x4, FMA2 over k-pairs ----
        unsigned long long acc[16];
        #pragma unroll
        for (int i = 0; i < 16; ++i) acc[i] = 0ull;

        const float* Wp = Ws + (size_t)(64*w)*64 + cg*4;
        #pragma unroll 4
        for (int kpl = 0; kpl < 64; ++kpl) {
            int ks = (2*(64*w + kpl)) ^ xr;
            unsigned long long a0 = *(const unsigned long long*)(Ab + ks);
            unsigned long long a1 = *(const unsigned long long*)(Ab + AS_STRIDE   + ks);
            unsigned long long a2 = *(const unsigned long long*)(Ab + 2*AS_STRIDE + ks);
            unsigned long long a3 = *(const unsigned long long*)(Ab + 3*AS_STRIDE + ks);
            ulonglong2 W0 = *(const ulonglong2*)(Wp);        // cols 2cg, 2cg+1
            ulonglong2 W1 = *(const ulonglong2*)(Wp + 32);   // cols 16+2cg, 17+2cg
            fma2(acc[ 0], a0, W0.x); fma2(acc[ 1], a0, W0.y);
            fma2(acc[ 2], a0, W1.x); fma2(acc[ 3], a0, W1.y);
            fma2(acc[ 4], a1, W0.x); fma2(acc[ 5], a1, W0.y);
            fma2(acc[ 6], a1, W1.x); fma2(acc[ 7], a1, W1.y);
            fma2(acc[ 8], a2, W0.x); fma2(acc[ 9], a2, W0.y);
            fma2(acc[10], a2, W1.x); fma2(acc[11], a2, W1.y);
            fma2(acc[12], a3, W0.x); fma2(acc[13], a3, W0.y);
            fma2(acc[14], a3, W1.x); fma2(acc[15], a3, W1.y);
            Wp += 64;
        }

        // horizontal add + partials to Red (conflict-free: RMS=34)
        {
            float s[16];
            #pragma unroll
            for (int i = 0; i < 16; ++i) {
                float lo, hi;
                asm("mov.b64 {%0, %1}, %2;" : "=f"(lo), "=f"(hi) : "l"(acc[i]));
                s[i] = lo + hi;
            }
            float* Rw = Red + w*RWS + (4*rg)*RMS + cg*2;
            #pragma unroll
            for (int i = 0; i < 4; ++i) {
                *(float2*)(Rw + i*RMS)      = make_float2(s[i*4+0], s[i*4+1]);
                *(float2*)(Rw + i*RMS + 16) = make_float2(s[i*4+2], s[i*4+3]);
            }
        }
        __syncthreads();   // bar3: partials -> reduce; As fully consumed

        // ---- off-path staging for t+1 (As low half is free now) ----
        if (t + 1 < TT) {
            if (layer == 0) {
                #pragma unroll
                for (int c = 0; c < 8; ++c) {
                    int mm = m0_st + 2*c;
                    float4 v = __ldg((const float4*)(x + ((size_t)(r*TM+mm)*TT + (t+1))*IDIM) + kk_st);
                    stage_f4(As, mm, kk_st, v);
                }
            } else {
                if (lane == 0) spin_ge(&g_done1[(t+1)*NBAND + r], NQ);  // L1 runs ahead; usually instant
                __syncwarp();
                #pragma unroll
                for (int c = 0; c < 8; ++c) {
                    int mm = m0_st + 2*c;
                    stage_f4(As, mm, kk_st,
                             ldcg4(&g_h1[(t+1)&(RING-1)][r*TM+mm][0] + kk_st*4));
                }
            }
        }

        // ---- cross-warp reduce, bias, tanh, store ----
        float2 acc2 = make_float2(0.f, 0.f);
        #pragma unroll
        for (int ww = 0; ww < 8; ++ww) {
            float2 v = *(const float2*)(Red + ww*RWS + m_out*RMS + c_out);
            acc2.x += v.x; acc2.y += v.y;
        }
        float2 res;
        res.x = fast_tanh(acc2.x + bias.x);
        res.y = fast_tanh(acc2.y + bias.y);

        if (layer == 0) {
            *(float2*)&g_h1[t&(RING-1)][brow_o][hcol_o] = res;
            if (t == TT-1)
                *(float2*)(out + (size_t)BB*TT*HH + (size_t)brow_o*HH + hcol_o) = res;
        } else {
            *(float2*)(out + ((size_t)brow_o*TT + t)*HH + hcol_o) = res;
            if (t == TT-1)
                *(float2*)(out + (size_t)BB*TT*HH + (size_t)BB*HH
                               + (size_t)brow_o*HH + hcol_o) = res;
        }

        __syncthreads();   // bar4: all stores done before release
        if (tid == 0) {
            int* ctr = (layer == 0) ? &g_done1[t*NBAND + r] : &g_done2[t*NBAND + r];
            red_release(ctr);
        }
    }
}

extern "C" void kernel_launch(void* const* d_in, const int* in_sizes, int n_in,
                              void* d_out, int out_size)
{
    const float* x   = (const float*)d_in[0];
    const float* h0  = (const float*)d_in[1];
    const float* Wih = (const float*)d_in[2];
    const float* bih = (const float*)d_in[3];
    const float* Whh = (const float*)d_in[4];
    const float* bhh = (const float*)d_in[5];
    float* out = (float*)d_out;

    const size_t smem_bytes = (size_t)SMEM_FLOATS * sizeof(float);
    cudaFuncSetAttribute(rnn_persistent,
                         cudaFuncAttributeMaxDynamicSharedMemorySize,
                         (int)smem_bytes);

    rnn_init_counters<<<(TT*NBAND + 255)/256, 256>>>();
    rnn_persistent<<<NCTA, NTHR, smem_bytes>>>(x, h0, Wih, bih, Whh, bhh, out);
}

// round 11
// speedup vs baseline: 1.2766x; 1.2766x over previous
#include <cuda_runtime.h>
#include <cstdint>
#include <cstddef>

// Problem dims
#define BB    64
#define TT    512
#define IDIM  512
#define HH    512
#define RING  8

// Tiling
#define TM    16
#define TN    32
#define NBAND (BB/TM)       // 4
#define NQ    (HH/TN)       // 16 (CTA-level releases)
#define NCTA  128
#define NTHR  256

#define AS_STRIDE 1028
#define RMS 34              // Red m-stride -> conflict-free partial STS
#define RWS (16*RMS)

// SMEM layout (floats)
#define AS_OFF  0
#define WS_OFF  (TM*AS_STRIDE)
#define RED_OFF (WS_OFF + 512*64)
#define SMEM_FLOATS (RED_OFF + 8*RWS)

__device__ float g_h1[RING][BB][HH];
__device__ int   g_done1[TT*NBAND];
__device__ int   g_done2[TT*NBAND];

__global__ void rnn_init_counters() {
    int i = blockIdx.x * blockDim.x + threadIdx.x;
    if (i < TT*NBAND) { g_done1[i] = 0; g_done2[i] = 0; }
}

__device__ __forceinline__ int ld_acq(const int* p) {
    int v;
    asm volatile("ld.acquire.gpu.global.u32 %0, [%1];" : "=r"(v) : "l"(p));
    return v;
}
__device__ __forceinline__ void red_release(int* p) {
    asm volatile("red.release.gpu.global.add.u32 [%0], %1;" :: "l"(p), "r"(1) : "memory");
}
__device__ __forceinline__ void spin_ge(const int* p, int target) {
    while (ld_acq(p) < target) { }
}
__device__ __forceinline__ void fma2(unsigned long long& acc,
                                     unsigned long long a, unsigned long long b) {
    asm("fma.rn.f32x2 %0, %1, %2, %0;" : "+l"(acc) : "l"(a), "l"(b));
}
__device__ __forceinline__ float4 ldcg4(const float* p) {
    return __ldcg((const float4*)p);
}

// tanh(x) = 1 - 2/(exp(2x)+1); ex2.approx + rcp.approx + 1 Newton (abs err ~1e-7)
__device__ __forceinline__ float fast_tanh(float v) {
    float e;
    asm("ex2.approx.f32 %0, %1;" : "=f"(e) : "f"(v * 2.8853900817779268f));
    float d = e + 1.0f;
    float r;
    asm("rcp.approx.f32 %0, %1;" : "=f"(r) : "f"(d));
    r = r * (2.0f - d * r);
    return 1.0f - 2.0f * r;
}

// Store one float4 (k = 4*kk..4*kk+3 of row mm) into swizzled row-major As.
__device__ __forceinline__ void stage_f4(float* As, int mm, int kk, float4 v) {
    int idx = (kk*4) ^ ((mm >> 2) * 8);
    *(float4*)&As[mm*AS_STRIDE + idx] = v;
}

__global__ void __launch_bounds__(NTHR, 1) rnn_persistent(
    const float* __restrict__ x,    // [B,T,I]
    const float* __restrict__ h0,   // [L,B,H]
    const float* __restrict__ Wih,  // [L,H,I]
    const float* __restrict__ bih,  // [L,H]
    const float* __restrict__ Whh,  // [L,H,H]
    const float* __restrict__ bhh,  // [L,H]
    float* __restrict__ out)        // [B,T,H] then [L,B,H]
{
    extern __shared__ float smem[];
    float* As  = smem + AS_OFF;   // [16][1028] row-major, k-index XOR-swizzled
    float* Ws  = smem + WS_OFF;   // [512 kp][64]
    float* Red = smem + RED_OFF;  // [8 w][16 m x RMS]

    const int bx    = blockIdx.x;
    const int layer = bx >> 6;
    const int j     = bx & 63;
    const int r     = j >> 4;
    const int q     = j & 15;
    const int tid   = threadIdx.x;
    const int w     = tid >> 5;          // warp id; GEMM kp slice [64w, 64w+64)
    const int lane  = tid & 31;
    const int rg    = lane & 3;
    const int cg    = lane >> 2;
    const bool on_path = (w >= 4);       // warps 4-7 own the recurrent K-half

    const float* Wi = Wih + (size_t)layer * HH * IDIM;
    const float* Wh = Whh + (size_t)layer * HH * HH;

    // one-time weight load: k-paired transposed; kp 0..255 = Wih, 256..511 = Whh
    for (int idx = tid; idx < TN*256; idx += NTHR) {
        int c   = idx >> 8;
        int kpl = idx & 255;
        float2 vi = __ldg((const float2*)(Wi + (size_t)(q*TN + c)*IDIM) + kpl);
        float2 vh = __ldg((const float2*)(Wh + (size_t)(q*TN + c)*HH)   + kpl);
        *(float2*)&Ws[(size_t)kpl*64 + c*2]       = vi;
        *(float2*)&Ws[(size_t)(256+kpl)*64 + c*2] = vh;
    }

    // per-warp staging constants: warp w owns As f4-columns [32w, 32w+32)
    const int c_st  = lane & 15;         // column offset 0..15 (also +16)
    const int mr_st = lane >> 4;         // row parity 0..1
    const int kk0   = 32*w + c_st;       // As f4-column (first)
    const int kk1   = kk0 + 16;          // As f4-column (second)
    // source f4 index within the 512-float operand vector:
    const int s0    = on_path ? (kk0 - 128) : kk0;
    const int s1    = on_path ? (kk1 - 128) : kk1;

    // output mapping: 2 outputs per thread
    const int o0     = 2*tid;
    const int m_out  = o0 >> 5;
    const int c_out  = o0 & 31;
    const int brow_o = r*TM + m_out;
    const int hcol_o = q*TN + c_out;
    float2 bias;
    bias.x = bih[layer*HH + hcol_o]   + bhh[layer*HH + hcol_o];
    bias.y = bih[layer*HH + hcol_o+1] + bhh[layer*HH + hcol_o+1];

    __syncthreads();

    const float* Ab = As + (4*rg)*AS_STRIDE;
    const int    xr = 8*rg;

    for (int t = 0; t < TT; ++t) {
        // ============ per-warp-group: wait + stage own columns + GEMM ============
        if (!on_path) {
            // ---- OFF group (warps 0-3): x_t (L0) or h1(t) (L1) ----
            if (layer == 0) {
                #pragma unroll
                for (int i = 0; i < 8; ++i) {
                    int mm = mr_st + 2*i;
                    const float4* xp = (const float4*)(x + ((size_t)(r*TM+mm)*TT + t)*IDIM);
                    stage_f4(As, mm, kk0, __ldg(xp + s0));
                    stage_f4(As, mm, kk1, __ldg(xp + s1));
                }
            } else {
                if (lane == 0) spin_ge(&g_done1[t*NBAND + r], NQ);
                __syncwarp();
                const float* hb = &g_h1[t&(RING-1)][r*TM][0];
                #pragma unroll
                for (int i = 0; i < 8; ++i) {
                    int mm = mr_st + 2*i;
                    const float* hp = hb + (size_t)mm*HH;
                    stage_f4(As, mm, kk0, ldcg4(hp + s0*4));
                    stage_f4(As, mm, kk1, ldcg4(hp + s1*4));
                }
            }
        } else {
            // ---- ON group (warps 4-7): recurrent h(t-1) ----
            if (layer == 0) {
                if (lane == 0) {
                    if (t > 0)     spin_ge(&g_done1[(t-1)*NBAND + r], NQ);
                    if (t >= RING) spin_ge(&g_done2[(t-RING)*NBAND + r], NQ);
                }
                __syncwarp();
                #pragma unroll
                for (int i = 0; i < 8; ++i) {
                    int mm = mr_st + 2*i;
                    int b  = r*TM + mm;
                    const float* hp = (t == 0) ? (h0 + (size_t)b*HH)
                                               : &g_h1[(t-1)&(RING-1)][b][0];
                    stage_f4(As, mm, kk0, ldcg4(hp + s0*4));
                    stage_f4(As, mm, kk1, ldcg4(hp + s1*4));
                }
            } else {
                if (lane == 0 && t > 0) spin_ge(&g_done2[(t-1)*NBAND + r], NQ);
                __syncwarp();
                #pragma unroll
                for (int i = 0; i < 8; ++i) {
                    int mm = mr_st + 2*i;
                    int b  = r*TM + mm;
                    const float* hp = (t == 0) ? (h0 + (size_t)BB*HH + (size_t)b*HH)
                                               : (out + ((size_t)b*TT + (t-1))*HH);
                    stage_f4(As, mm, kk0, ldcg4(hp + s0*4));
                    stage_f4(As, mm, kk1, ldcg4(hp + s1*4));
                }
            }
        }
        __syncwarp();   // warp reads only its own staged columns

        // ---- GEMM: warp k-slice kp [64w,64w+64), thread 4x4, FMA2 ----
        unsigned long long acc[16];
        #pragma unroll
        for (int i = 0; i < 16; ++i) acc[i] = 0ull;

        const float* Wp = Ws + (size_t)(64*w)*64 + cg*4;
        #pragma unroll 4
        for (int kpl = 0; kpl < 64; ++kpl) {
            int ks = (2*(64*w + kpl)) ^ xr;
            unsigned long long a0 = *(const unsigned long long*)(Ab + ks);
            unsigned long long a1 = *(const unsigned long long*)(Ab + AS_STRIDE   + ks);
            unsigned long long a2 = *(const unsigned long long*)(Ab + 2*AS_STRIDE + ks);
            unsigned long long a3 = *(const unsigned long long*)(Ab + 3*AS_STRIDE + ks);
            ulonglong2 W0 = *(const ulonglong2*)(Wp);        // cols 2cg, 2cg+1
            ulonglong2 W1 = *(const ulonglong2*)(Wp + 32);   // cols 16+2cg, 17+2cg
            fma2(acc[ 0], a0, W0.x); fma2(acc[ 1], a0, W0.y);
            fma2(acc[ 2], a0, W1.x); fma2(acc[ 3], a0, W1.y);
            fma2(acc[ 4], a1, W0.x); fma2(acc[ 5], a1, W0.y);
            fma2(acc[ 6], a1, W1.x); fma2(acc[ 7], a1, W1.y);
            fma2(acc[ 8], a2, W0.x); fma2(acc[ 9], a2, W0.y);
            fma2(acc[10], a2, W1.x); fma2(acc[11], a2, W1.y);
            fma2(acc[12], a3, W0.x); fma2(acc[13], a3, W0.y);
            fma2(acc[14], a3, W1.x); fma2(acc[15], a3, W1.y);
            Wp += 64;
        }

        // horizontal add + partials to Red (warp-private slice; RMS=34 conflict-free)
        {
            float s[16];
            #pragma unroll
            for (int i = 0; i < 16; ++i) {
                float lo, hi;
                asm("mov.b64 {%0, %1}, %2;" : "=f"(lo), "=f"(hi) : "l"(acc[i]));
                s[i] = lo + hi;
            }
            float* Rw = Red + w*RWS + (4*rg)*RMS + cg*2;
            #pragma unroll
            for (int i = 0; i < 4; ++i) {
                *(float2*)(Rw + i*RMS)      = make_float2(s[i*4+0], s[i*4+1]);
                *(float2*)(Rw + i*RMS + 16) = make_float2(s[i*4+2], s[i*4+3]);
            }
        }
        __syncthreads();   // join both warp groups: partials -> reduce

        // ---- cross-warp reduce, bias, tanh, store ----
        float2 acc2 = make_float2(0.f, 0.f);
        #pragma unroll
        for (int ww = 0; ww < 8; ++ww) {
            float2 v = *(const float2*)(Red + ww*RWS + m_out*RMS + c_out);
            acc2.x += v.x; acc2.y += v.y;
        }
        float2 res;
        res.x = fast_tanh(acc2.x + bias.x);
        res.y = fast_tanh(acc2.y + bias.y);

        if (layer == 0) {
            *(float2*)&g_h1[t&(RING-1)][brow_o][hcol_o] = res;
            if (t == TT-1)
                *(float2*)(out + (size_t)BB*TT*HH + (size_t)brow_o*HH + hcol_o) = res;
        } else {
            *(float2*)(out + ((size_t)brow_o*TT + t)*HH + hcol_o) = res;
            if (t == TT-1)
                *(float2*)(out + (size_t)BB*TT*HH + (size_t)BB*HH
                               + (size_t)brow_o*HH + hcol_o) = res;
        }

        __syncthreads();   // all stores done before release
        if (tid == 0) {
            int* ctr = (layer == 0) ? &g_done1[t*NBAND + r] : &g_done2[t*NBAND + r];
            red_release(ctr);
        }
    }
}

extern "C" void kernel_launch(void* const* d_in, const int* in_sizes, int n_in,
                              void* d_out, int out_size)
{
    const float* x   = (const float*)d_in[0];
    const float* h0  = (const float*)d_in[1];
    const float* Wih = (const float*)d_in[2];
    const float* bih = (const float*)d_in[3];
    const float* Whh = (const float*)d_in[4];
    const float* bhh = (const float*)d_in[5];
    float* out = (float*)d_out;

    const size_t smem_bytes = (size_t)SMEM_FLOATS * sizeof(float);
    cudaFuncSetAttribute(rnn_persistent,
                         cudaFuncAttributeMaxDynamicSharedMemorySize,
                         (int)smem_bytes);

    rnn_init_counters<<<(TT*NBAND + 255)/256, 256>>>();
    rnn_persistent<<<NCTA, NTHR, smem_bytes>>>(x, h0, Wih, bih, Whh, bhh, out);
}